// round 10
// baseline (speedup 1.0000x reference)
#include <cuda_runtime.h>
#include <cuda_fp16.h>
#include <cstdint>
#include <cstddef>

#define NT 2048
#define RST 144

// ---- smem layout (bytes) ----
#define BUF0   0          // h1 slot 0: [64][72] half
#define BUF1   9216       // h1 slot 1
#define A2H0   18432      // h2 buffer 0
#define A2H1   27648      // h2 buffer 1
#define B1H    36864      // B tiles: 208*144 = 29952 each
#define B1L    66816
#define B2AH   96768
#define B2AL   126720
#define B2BH   156672
#define B2BL   186624
#define O_WL   216576
#define O_PART 216832     // [64][8] float
#define SMEM_TOTAL 219136

__device__ __forceinline__ uint32_t s2u(const void* p){
    uint32_t a;
    asm("{ .reg .u64 t; cvta.to.shared.u64 t, %1; cvt.u32.u64 %0, t; }" : "=r"(a) : "l"(p));
    return a;
}
__device__ __forceinline__ void ldsm4(uint32_t* r, uint32_t a){
    asm volatile("ldmatrix.sync.aligned.m8n8.x4.shared.b16 {%0,%1,%2,%3}, [%4];"
        : "=r"(r[0]),"=r"(r[1]),"=r"(r[2]),"=r"(r[3]) : "r"(a));
}
__device__ __forceinline__ void mma16816(float* c, const uint32_t* a, uint32_t b0, uint32_t b1){
    asm volatile("mma.sync.aligned.m16n8k16.row.col.f32.f16.f16.f32 "
        "{%0,%1,%2,%3}, {%4,%5,%6,%7}, {%8,%9}, {%0,%1,%2,%3};"
        : "+f"(c[0]),"+f"(c[1]),"+f"(c[2]),"+f"(c[3])
        : "r"(a[0]),"r"(a[1]),"r"(a[2]),"r"(a[3]), "r"(b0),"r"(b1));
}
__device__ __forceinline__ void nbar_sync(int id, int cnt){
    asm volatile("bar.sync %0, %1;" :: "r"(id), "r"(cnt) : "memory");
}
__device__ __forceinline__ void nbar_arrive(int id, int cnt){
    asm volatile("bar.arrive %0, %1;" :: "r"(id), "r"(cnt) : "memory");
}
__device__ __forceinline__ float fast_sig(float x){
    float e = __expf(-x);
    float r;
    asm("rcp.approx.f32 %0, %1;" : "=f"(r) : "f"(1.0f + e));
    return r;
}
__device__ __forceinline__ float fast_tanh(float x){
    return fmaf(2.0f, fast_sig(x + x), -1.0f);
}
__device__ __forceinline__ float epi_update(const float* gc, float& c, int p){
    float r0 = __shfl_xor_sync(0xFFFFFFFFu, gc[0], 1);
    float r1 = __shfl_xor_sync(0xFFFFFFFFu, gc[1], 1);
    float r2 = __shfl_xor_sync(0xFFFFFFFFu, gc[2], 1);
    float r3 = __shfl_xor_sync(0xFFFFFFFFu, gc[3], 1);
    float gi = p ? r2 : gc[0];
    float gf = p ? r3 : gc[1];
    float gG = p ? gc[2] : r0;
    float gO = p ? gc[3] : r1;
    float cn = fast_sig(gf)*c + fast_sig(gi)*fast_tanh(gG);
    c = cn;
    return fast_sig(gO)*fast_tanh(cn);
}
// stage [204-row] weight block into [208][72] fp16 hi + residual-lo tiles
__device__ void stageB(const float* W, const float* wx, const float* ba, const float* bb,
                       half* hi, half* lo, int tid){
    for (int i = tid; i < 208*72; i += 512){
        int n = i / 72, k = i - n*72;
        float v = 0.0f;
        if (n < 204){
            int u = n >> 2, g = n & 3, row = g*51 + u;
            if (k < 51)                 v = W[row*51 + k];
            else if (k == 51 && wx)     v = wx[row];
            else if (k == 52 && ba)     v = ba[row] + bb[row];
        }
        half h = __float2half(v);
        hi[i] = h;
        lo[i] = __float2half(v - __half2float(h));
    }
}

__global__ void __launch_bounds__(512, 1)
lstm_ws_kernel(const float* __restrict__ input,
               const float* __restrict__ Wih1, const float* __restrict__ Whh1,
               const float* __restrict__ bih1, const float* __restrict__ bhh1,
               const float* __restrict__ Wih2, const float* __restrict__ Whh2,
               const float* __restrict__ bih2, const float* __restrict__ bhh2,
               const float* __restrict__ Wlin, const float* __restrict__ blin,
               float* __restrict__ out)
{
    extern __shared__ char smem[];
    const int tid  = threadIdx.x;
    const int lane = tid & 31;
    const int wid  = tid >> 5;
    const int b0   = blockIdx.x * 64;
    const uint32_t sb = s2u(smem);

    half* buf[2] = { (half*)(smem + BUF0), (half*)(smem + BUF1) };
    half* h2b[2] = { (half*)(smem + A2H0), (half*)(smem + A2H1) };

    // ---- init: stage weights, zero state ----
    stageB(Whh1, Wih1, bih1, bhh1, (half*)(smem + B1H),  (half*)(smem + B1L),  tid);
    stageB(Wih2, 0,    bih2, bhh2, (half*)(smem + B2AH), (half*)(smem + B2AL), tid);
    stageB(Whh2, 0,    0,    0,    (half*)(smem + B2BH), (half*)(smem + B2BL), tid);
    for (int i = tid; i < 36864/4; i += 512) ((uint32_t*)(smem + BUF0))[i] = 0u;  // h1x2, h2x2
    for (int i = tid; i < 64*8; i += 512) ((float*)(smem + O_PART))[i] = 0.0f;
    if (tid < 52) ((float*)(smem + O_WL))[tid] = (tid < 51) ? Wlin[tid] : 0.0f;
    __syncthreads();
    if (tid < 64){
        buf[0][tid*72 + 51] = __float2half(input[(size_t)(b0 + tid)*NT]);  // x(0)
        buf[0][tid*72 + 52] = __float2half(1.0f);
        buf[1][tid*72 + 52] = __float2half(1.0f);
    }
    __syncthreads();

    const int g   = lane >> 2;
    const int tig = lane & 3;
    const int p   = tig & 1;
    const uint32_t aro  = (uint32_t)(((lane>>3)&1)*8*RST + (lane&7)*RST + ((lane>>4)&1)*16);
    const uint32_t bro4 = (uint32_t)((lane&7)*RST + ((lane>>3)&3)*16);
    const float* wlS = (const float*)(smem + O_WL);
    float* part = (float*)(smem + O_PART);

    if (wid < 6){
        // ================= X group: layer-1 recurrence (producer) =================
        const int mg = wid & 1, qx = wid >> 1;
        const int ns = qx * 9;
        const int nt = (qx == 2) ? 8 : 9;
        const int m0 = mg * 32;
        const int er0 = m0 + p*8 + g, er1 = er0 + 16;
        const uint32_t ab[2][2] = {
            { sb + BUF0 + m0*RST + aro, sb + BUF0 + m0*RST + aro + 16*RST },
            { sb + BUF1 + m0*RST + aro, sb + BUF1 + m0*RST + aro + 16*RST } };
        const uint32_t b1hb = sb + B1H + bro4, b1lb = sb + B1L + bro4;

        float c1[2][9];
        #pragma unroll
        for (int j = 0; j < 9; j++){ c1[0][j] = 0.0f; c1[1][j] = 0.0f; }

        uint32_t fa[2][16];
        #pragma unroll
        for (int kc = 0; kc < 4; kc++){
            ldsm4(&fa[0][kc*4], ab[0][0] + kc*32);
            ldsm4(&fa[1][kc*4], ab[0][1] + kc*32);
        }

        #pragma unroll 1
        for (int t = 0; t < NT; t++){
            const int s = t & 1;
            if (t >= 2) nbar_sync(3 + s, 512);            // wait slot s free
            float xv = 0.0f;
            if (tid < 64 && t + 1 < NT) xv = input[(size_t)(b0 + tid)*NT + t + 1];
            half* bh = buf[s];

            #pragma unroll
            for (int j = 0; j < 9; j++){
                if (j >= nt) break;
                const uint32_t nofs = (uint32_t)((ns + j)*8*RST);
                // 4 independent chains: {hi,lo} x {tile0,tile1}, 4-deep each
                float ha[4] = {0,0,0,0}, hb[4] = {0,0,0,0};
                float la[4] = {0,0,0,0}, lb[4] = {0,0,0,0};
                #pragma unroll
                for (int kc2 = 0; kc2 < 2; kc2++){
                    uint32_t b4[4], b4l[4];
                    ldsm4(b4,  b1hb + nofs + kc2*64);
                    ldsm4(b4l, b1lb + nofs + kc2*64);
                    mma16816(ha, &fa[0][(2*kc2)*4],   b4[0],  b4[1]);
                    mma16816(hb, &fa[1][(2*kc2)*4],   b4[0],  b4[1]);
                    mma16816(la, &fa[0][(2*kc2)*4],   b4l[0], b4l[1]);
                    mma16816(lb, &fa[1][(2*kc2)*4],   b4l[0], b4l[1]);
                    mma16816(ha, &fa[0][(2*kc2+1)*4], b4[2],  b4[3]);
                    mma16816(hb, &fa[1][(2*kc2+1)*4], b4[2],  b4[3]);
                    mma16816(la, &fa[0][(2*kc2+1)*4], b4l[2], b4l[3]);
                    mma16816(lb, &fa[1][(2*kc2+1)*4], b4l[2], b4l[3]);
                }
                float g1a[4], g1b[4];
                #pragma unroll
                for (int r = 0; r < 4; r++){ g1a[r] = ha[r] + la[r]; g1b[r] = hb[r] + lb[r]; }
                float h0 = epi_update(g1a, c1[0][j], p);
                float h1 = epi_update(g1b, c1[1][j], p);
                int u = 2*(ns + j) + (tig >> 1);
                if (u < 51){
                    bh[er0*72 + u] = __float2half(h0);
                    bh[er1*72 + u] = __float2half(h1);
                }
            }
            if (tid < 64 && t + 1 < NT) bh[tid*72 + 51] = __float2half(xv);
            nbar_sync(6, 192);                            // intra-X: buf[s] complete (drains STS)
            nbar_arrive(1 + s, 512);                      // signal full[s] to Y
            #pragma unroll
            for (int kc = 0; kc < 4; kc++){               // reload h1(t) for t+1
                ldsm4(&fa[0][kc*4], ab[s][0] + kc*32);
                ldsm4(&fa[1][kc*4], ab[s][1] + kc*32);
            }
        }
    } else {
        // ================= Y group: layer-2 + output (consumer) =================
        const int yw = wid - 6;
        const int mg = yw & 1, qy = yw >> 1;
        const int nt = (qy == 0) ? 6 : 5;
        const int ns = (qy == 0) ? 0 : 6 + 5*(qy - 1);
        const int m0 = mg * 32;
        const int er0 = m0 + p*8 + g, er1 = er0 + 16;
        const uint32_t ab[2][2] = {
            { sb + BUF0 + m0*RST + aro, sb + BUF0 + m0*RST + aro + 16*RST },
            { sb + BUF1 + m0*RST + aro, sb + BUF1 + m0*RST + aro + 16*RST } };
        const uint32_t a2rb[2][2] = {
            { sb + A2H0 + m0*RST + aro, sb + A2H0 + m0*RST + aro + 16*RST },
            { sb + A2H1 + m0*RST + aro, sb + A2H1 + m0*RST + aro + 16*RST } };
        const uint32_t bahb = sb + B2AH + bro4, balb = sb + B2AL + bro4;
        const uint32_t bbhb = sb + B2BH + bro4, bblb = sb + B2BL + bro4;
        const float blin0 = blin[0];

        float c2[2][6];
        #pragma unroll
        for (int j = 0; j < 6; j++){ c2[0][j] = 0.0f; c2[1][j] = 0.0f; }

        uint32_t fa1[2][16], fa2[2][16];
        #pragma unroll
        for (int kc = 0; kc < 4; kc++){                   // h2(-1) = 0 from buffer 0
            ldsm4(&fa2[0][kc*4], a2rb[0][0] + kc*32);
            ldsm4(&fa2[1][kc*4], a2rb[0][1] + kc*32);
        }

        #pragma unroll 1
        for (int t = 0; t < NT; t++){
            const int s  = t & 1;
            const int ws = (t + 1) & 1;                   // h2 write/next-read buffer
            half* a2w = h2b[ws];
            nbar_sync(1 + s, 512);                        // wait full[s]: h1(t) ready
            #pragma unroll
            for (int kc = 0; kc < 4; kc++){
                ldsm4(&fa1[0][kc*4], ab[s][0] + kc*32);
                ldsm4(&fa1[1][kc*4], ab[s][1] + kc*32);
            }
            float pd0 = 0.0f, pd1 = 0.0f;
            #pragma unroll
            for (int j = 0; j < 6; j++){
                if (j >= nt) break;
                const uint32_t nofs = (uint32_t)((ns + j)*8*RST);
                // 4 independent chains: {fa1-side, fa2-side} x {tile0, tile1}, 8-deep each
                float xa[4] = {0,0,0,0}, xb[4] = {0,0,0,0};
                float ya[4] = {0,0,0,0}, yb[4] = {0,0,0,0};
                #pragma unroll
                for (int kc2 = 0; kc2 < 2; kc2++){
                    uint32_t b4a[4], b4b[4];
                    ldsm4(b4a, bahb + nofs + kc2*64);
                    ldsm4(b4b, bbhb + nofs + kc2*64);
                    mma16816(xa, &fa1[0][(2*kc2)*4],   b4a[0], b4a[1]);
                    mma16816(xb, &fa1[1][(2*kc2)*4],   b4a[0], b4a[1]);
                    mma16816(ya, &fa2[0][(2*kc2)*4],   b4b[0], b4b[1]);
                    mma16816(yb, &fa2[1][(2*kc2)*4],   b4b[0], b4b[1]);
                    mma16816(xa, &fa1[0][(2*kc2+1)*4], b4a[2], b4a[3]);
                    mma16816(xb, &fa1[1][(2*kc2+1)*4], b4a[2], b4a[3]);
                    mma16816(ya, &fa2[0][(2*kc2+1)*4], b4b[2], b4b[3]);
                    mma16816(yb, &fa2[1][(2*kc2+1)*4], b4b[2], b4b[3]);
                }
                #pragma unroll
                for (int kc2 = 0; kc2 < 2; kc2++){
                    uint32_t b4a[4], b4b[4];
                    ldsm4(b4a, balb + nofs + kc2*64);
                    ldsm4(b4b, bblb + nofs + kc2*64);
                    mma16816(xa, &fa1[0][(2*kc2)*4],   b4a[0], b4a[1]);
                    mma16816(xb, &fa1[1][(2*kc2)*4],   b4a[0], b4a[1]);
                    mma16816(ya, &fa2[0][(2*kc2)*4],   b4b[0], b4b[1]);
                    mma16816(yb, &fa2[1][(2*kc2)*4],   b4b[0], b4b[1]);
                    mma16816(xa, &fa1[0][(2*kc2+1)*4], b4a[2], b4a[3]);
                    mma16816(xb, &fa1[1][(2*kc2+1)*4], b4a[2], b4a[3]);
                    mma16816(ya, &fa2[0][(2*kc2+1)*4], b4b[2], b4b[3]);
                    mma16816(yb, &fa2[1][(2*kc2+1)*4], b4b[2], b4b[3]);
                }
                float g2a[4], g2b[4];
                #pragma unroll
                for (int r = 0; r < 4; r++){ g2a[r] = xa[r] + ya[r]; g2b[r] = xb[r] + yb[r]; }
                float h0 = epi_update(g2a, c2[0][j], p);
                float h1 = epi_update(g2b, c2[1][j], p);
                int u = 2*(ns + j) + (tig >> 1);
                if (u < 51){
                    a2w[er0*72 + u] = __float2half(h0);
                    a2w[er1*72 + u] = __float2half(h1);
                }
                float wlv = wlS[2*(ns + j) + (tig >> 1)];
                pd0 = fmaf(h0, wlv, pd0);
                pd1 = fmaf(h1, wlv, pd1);
            }
            pd0 += __shfl_xor_sync(0xFFFFFFFFu, pd0, 2);
            pd1 += __shfl_xor_sync(0xFFFFFFFFu, pd1, 2);
            if (tig < 2){
                part[er0*8 + qy] = pd0;
                part[er1*8 + qy] = pd1;
            }
            nbar_sync(5, 320);                            // intra-Y: h2(t) + part done (drains STS)
            if (tid >= 256 && tid < 320){
                const int ot = tid - 256;
                const float* pr = part + ot*8;
                out[(size_t)(b0 + ot)*NT + t] =
                    (pr[0] + pr[1]) + (pr[2] + pr[3]) + pr[4] + blin0;
            }
            #pragma unroll
            for (int kc = 0; kc < 4; kc++){               // reload h2(t) from buffer ws
                ldsm4(&fa2[0][kc*4], a2rb[ws][0] + kc*32);
                ldsm4(&fa2[1][kc*4], a2rb[ws][1] + kc*32);
            }
            if (t < NT - 2) nbar_arrive(3 + s, 512);      // release slot s to X
        }
    }
}

extern "C" void kernel_launch(void* const* d_in, const int* in_sizes, int n_in,
                              void* d_out, int out_size)
{
    (void)in_sizes; (void)n_in; (void)out_size;
    const float* input = (const float*)d_in[0];
    const float* Wih1  = (const float*)d_in[1];
    const float* Whh1  = (const float*)d_in[2];
    const float* bih1  = (const float*)d_in[3];
    const float* bhh1  = (const float*)d_in[4];
    const float* Wih2  = (const float*)d_in[5];
    const float* Whh2  = (const float*)d_in[6];
    const float* bih2  = (const float*)d_in[7];
    const float* bhh2  = (const float*)d_in[8];
    const float* Wlin  = (const float*)d_in[9];
    const float* blin  = (const float*)d_in[10];
    float* out = (float*)d_out;

    cudaFuncSetAttribute(lstm_ws_kernel, cudaFuncAttributeMaxDynamicSharedMemorySize, SMEM_TOTAL);
    lstm_ws_kernel<<<128, 512, SMEM_TOTAL>>>(input, Wih1, Whh1, bih1, bhh1,
                                             Wih2, Whh2, bih2, bhh2, Wlin, blin, out);
}

// round 11
// speedup vs baseline: 1.0403x; 1.0403x over previous
#include <cuda_runtime.h>
#include <cuda_fp16.h>
#include <cstdint>
#include <cstddef>

#define NT 2048
#define RST 144

// ---- smem layout (bytes) ----
#define BUF0   0          // h1 slot 0: [64][72] half
#define BUF1   9216       // h1 slot 1
#define A2H0   18432      // h2 buffer 0
#define A2H1   27648      // h2 buffer 1
#define B1H    36864      // B tiles: 208*144 = 29952 each
#define B1L    66816
#define B2AH   96768
#define B2AL   126720
#define B2BH   156672
#define B2BL   186624
#define O_WL   216576
#define O_PART 216832     // [64][8] float
#define SMEM_TOTAL 219136

__device__ __forceinline__ uint32_t s2u(const void* p){
    uint32_t a;
    asm("{ .reg .u64 t; cvta.to.shared.u64 t, %1; cvt.u32.u64 %0, t; }" : "=r"(a) : "l"(p));
    return a;
}
__device__ __forceinline__ void ldsm4(uint32_t* r, uint32_t a){
    asm volatile("ldmatrix.sync.aligned.m8n8.x4.shared.b16 {%0,%1,%2,%3}, [%4];"
        : "=r"(r[0]),"=r"(r[1]),"=r"(r[2]),"=r"(r[3]) : "r"(a));
}
__device__ __forceinline__ void mma16816(float* c, const uint32_t* a, uint32_t b0, uint32_t b1){
    asm volatile("mma.sync.aligned.m16n8k16.row.col.f32.f16.f16.f32 "
        "{%0,%1,%2,%3}, {%4,%5,%6,%7}, {%8,%9}, {%0,%1,%2,%3};"
        : "+f"(c[0]),"+f"(c[1]),"+f"(c[2]),"+f"(c[3])
        : "r"(a[0]),"r"(a[1]),"r"(a[2]),"r"(a[3]), "r"(b0),"r"(b1));
}
__device__ __forceinline__ void nbar_sync(int id, int cnt){
    asm volatile("bar.sync %0, %1;" :: "r"(id), "r"(cnt) : "memory");
}
__device__ __forceinline__ void nbar_arrive(int id, int cnt){
    asm volatile("bar.arrive %0, %1;" :: "r"(id), "r"(cnt) : "memory");
}
__device__ __forceinline__ float fast_sig(float x){
    float e = __expf(-x);
    float r;
    asm("rcp.approx.f32 %0, %1;" : "=f"(r) : "f"(1.0f + e));
    return r;
}
__device__ __forceinline__ float fast_tanh(float x){
    return fmaf(2.0f, fast_sig(x + x), -1.0f);
}
__device__ __forceinline__ float epi_update(const float* gc, float& c, int p){
    float r0 = __shfl_xor_sync(0xFFFFFFFFu, gc[0], 1);
    float r1 = __shfl_xor_sync(0xFFFFFFFFu, gc[1], 1);
    float r2 = __shfl_xor_sync(0xFFFFFFFFu, gc[2], 1);
    float r3 = __shfl_xor_sync(0xFFFFFFFFu, gc[3], 1);
    float gi = p ? r2 : gc[0];
    float gf = p ? r3 : gc[1];
    float gG = p ? gc[2] : r0;
    float gO = p ? gc[3] : r1;
    float cn = fast_sig(gf)*c + fast_sig(gi)*fast_tanh(gG);
    c = cn;
    return fast_sig(gO)*fast_tanh(cn);
}
// stage [204-row] weight block into [208][72] fp16 hi + residual-lo tiles
__device__ void stageB(const float* W, const float* wx, const float* ba, const float* bb,
                       half* hi, half* lo, int tid){
    for (int i = tid; i < 208*72; i += 512){
        int n = i / 72, k = i - n*72;
        float v = 0.0f;
        if (n < 204){
            int u = n >> 2, g = n & 3, row = g*51 + u;
            if (k < 51)                 v = W[row*51 + k];
            else if (k == 51 && wx)     v = wx[row];
            else if (k == 52 && ba)     v = ba[row] + bb[row];
        }
        half h = __float2half(v);
        hi[i] = h;
        lo[i] = __float2half(v - __half2float(h));
    }
}

__global__ void __launch_bounds__(512, 1)
lstm_ws_kernel(const float* __restrict__ input,
               const float* __restrict__ Wih1, const float* __restrict__ Whh1,
               const float* __restrict__ bih1, const float* __restrict__ bhh1,
               const float* __restrict__ Wih2, const float* __restrict__ Whh2,
               const float* __restrict__ bih2, const float* __restrict__ bhh2,
               const float* __restrict__ Wlin, const float* __restrict__ blin,
               float* __restrict__ out)
{
    extern __shared__ char smem[];
    const int tid  = threadIdx.x;
    const int lane = tid & 31;
    const int wid  = tid >> 5;
    const int b0   = blockIdx.x * 64;
    const uint32_t sb = s2u(smem);

    half* buf[2] = { (half*)(smem + BUF0), (half*)(smem + BUF1) };
    half* h2b[2] = { (half*)(smem + A2H0), (half*)(smem + A2H1) };

    // ---- init: stage weights, zero state ----
    stageB(Whh1, Wih1, bih1, bhh1, (half*)(smem + B1H),  (half*)(smem + B1L),  tid);
    stageB(Wih2, 0,    bih2, bhh2, (half*)(smem + B2AH), (half*)(smem + B2AL), tid);
    stageB(Whh2, 0,    0,    0,    (half*)(smem + B2BH), (half*)(smem + B2BL), tid);
    for (int i = tid; i < 36864/4; i += 512) ((uint32_t*)(smem + BUF0))[i] = 0u;  // h1 x2, h2 x2
    for (int i = tid; i < 64*8; i += 512) ((float*)(smem + O_PART))[i] = 0.0f;
    if (tid < 52) ((float*)(smem + O_WL))[tid] = (tid < 51) ? Wlin[tid] : 0.0f;
    __syncthreads();
    if (tid < 64){
        buf[0][tid*72 + 51] = __float2half(input[(size_t)(b0 + tid)*NT]);  // x(0)
        buf[0][tid*72 + 52] = __float2half(1.0f);
        buf[1][tid*72 + 52] = __float2half(1.0f);
    }
    __syncthreads();

    const int g   = lane >> 2;
    const int tig = lane & 3;
    const int p   = tig & 1;
    const uint32_t aro  = (uint32_t)(((lane>>3)&1)*8*RST + (lane&7)*RST + ((lane>>4)&1)*16);
    const uint32_t bro4 = (uint32_t)((lane&7)*RST + ((lane>>3)&3)*16);
    const float* wlS = (const float*)(smem + O_WL);
    float* part = (float*)(smem + O_PART);

    if (wid < 6){
        // ================= X group: layer-1 recurrence (producer) =================
        const int mg = wid & 1, qx = wid >> 1;
        const int ns = qx * 9;
        const int nt = (qx == 2) ? 8 : 9;
        const int m0 = mg * 32;
        const int er0 = m0 + p*8 + g, er1 = er0 + 16;
        const uint32_t ab[2][2] = {
            { sb + BUF0 + m0*RST + aro, sb + BUF0 + m0*RST + aro + 16*RST },
            { sb + BUF1 + m0*RST + aro, sb + BUF1 + m0*RST + aro + 16*RST } };
        const uint32_t b1hb = sb + B1H + bro4, b1lb = sb + B1L + bro4;

        float c1[2][9];
        #pragma unroll
        for (int j = 0; j < 9; j++){ c1[0][j] = 0.0f; c1[1][j] = 0.0f; }

        uint32_t fa[2][16];
        #pragma unroll
        for (int kc = 0; kc < 4; kc++){
            ldsm4(&fa[0][kc*4], ab[0][0] + kc*32);
            ldsm4(&fa[1][kc*4], ab[0][1] + kc*32);
        }

        #pragma unroll 1
        for (int t = 0; t < NT; t++){
            const int s = t & 1;
            if (t >= 2) nbar_sync(3 + s, 512);            // wait slot s free
            float xv = 0.0f;
            if (tid < 64 && t + 1 < NT) xv = input[(size_t)(b0 + tid)*NT + t + 1];
            half* bh = buf[s];

            #pragma unroll
            for (int j = 0; j < 9; j++){
                if (j >= nt) break;
                const uint32_t nofs = (uint32_t)((ns + j)*8*RST);
                float g1a[4] = {0,0,0,0}, g1b[4] = {0,0,0,0};
                uint32_t b4[4];
                #pragma unroll
                for (int kc2 = 0; kc2 < 2; kc2++){
                    ldsm4(b4, b1hb + nofs + kc2*64);
                    mma16816(g1a, &fa[0][(2*kc2)*4],   b4[0], b4[1]);
                    mma16816(g1b, &fa[1][(2*kc2)*4],   b4[0], b4[1]);
                    mma16816(g1a, &fa[0][(2*kc2+1)*4], b4[2], b4[3]);
                    mma16816(g1b, &fa[1][(2*kc2+1)*4], b4[2], b4[3]);
                }
                #pragma unroll
                for (int kc2 = 0; kc2 < 2; kc2++){
                    ldsm4(b4, b1lb + nofs + kc2*64);
                    mma16816(g1a, &fa[0][(2*kc2)*4],   b4[0], b4[1]);
                    mma16816(g1b, &fa[1][(2*kc2)*4],   b4[0], b4[1]);
                    mma16816(g1a, &fa[0][(2*kc2+1)*4], b4[2], b4[3]);
                    mma16816(g1b, &fa[1][(2*kc2+1)*4], b4[2], b4[3]);
                }
                float h0 = epi_update(g1a, c1[0][j], p);
                float h1 = epi_update(g1b, c1[1][j], p);
                int u = 2*(ns + j) + (tig >> 1);
                if (u < 51){
                    bh[er0*72 + u] = __float2half(h0);
                    bh[er1*72 + u] = __float2half(h1);
                }
            }
            if (tid < 64 && t + 1 < NT) bh[tid*72 + 51] = __float2half(xv);
            nbar_sync(6, 192);                            // intra-X: buf[s] complete (drains STS)
            nbar_arrive(1 + s, 512);                      // signal full[s] to Y
            #pragma unroll
            for (int kc = 0; kc < 4; kc++){               // reload h1(t) for t+1
                ldsm4(&fa[0][kc*4], ab[s][0] + kc*32);
                ldsm4(&fa[1][kc*4], ab[s][1] + kc*32);
            }
        }
    } else {
        // ================= Y group: layer-2 + output (consumer) =================
        const int yw = wid - 6;
        const int mg = yw & 1, qy = yw >> 1;
        const int nt = (qy == 0) ? 6 : 5;
        const int ns = (qy == 0) ? 0 : 6 + 5*(qy - 1);
        const int m0 = mg * 32;
        const int er0 = m0 + p*8 + g, er1 = er0 + 16;
        const uint32_t ab[2][2] = {
            { sb + BUF0 + m0*RST + aro, sb + BUF0 + m0*RST + aro + 16*RST },
            { sb + BUF1 + m0*RST + aro, sb + BUF1 + m0*RST + aro + 16*RST } };
        const uint32_t a2base0 = sb + A2H0 + m0*RST + aro;
        const uint32_t a2base1 = sb + A2H1 + m0*RST + aro;
        const uint32_t bahb = sb + B2AH + bro4, balb = sb + B2AL + bro4;
        const uint32_t bbhb = sb + B2BH + bro4, bblb = sb + B2BL + bro4;
        const float blin0 = blin[0];

        float c2[2][6], wlr[6];
        #pragma unroll
        for (int j = 0; j < 6; j++){
            c2[0][j] = 0.0f; c2[1][j] = 0.0f;
            wlr[j] = wlS[2*(ns + j) + (tig >> 1)];
        }
        uint32_t fa1[2][16], fa2[2][16];
        #pragma unroll
        for (int kc = 0; kc < 4; kc++){                   // h2(-1) = 0 from buffer 0
            ldsm4(&fa2[0][kc*4], a2base0 + kc*32);
            ldsm4(&fa2[1][kc*4], a2base0 + 16*RST + kc*32);
        }

        #pragma unroll 1
        for (int t = 0; t < NT; t++){
            const int s  = t & 1;
            const int ws = (t + 1) & 1;                   // h2 write/next-read buffer
            half* a2w = h2b[ws];
            nbar_sync(1 + s, 512);                        // wait full[s]: h1(t) ready
            #pragma unroll
            for (int kc = 0; kc < 4; kc++){
                ldsm4(&fa1[0][kc*4], ab[s][0] + kc*32);
                ldsm4(&fa1[1][kc*4], ab[s][1] + kc*32);
            }
            float pd0 = 0.0f, pd1 = 0.0f;
            #pragma unroll
            for (int j = 0; j < 6; j++){
                if (j >= nt) break;
                const uint32_t nofs = (uint32_t)((ns + j)*8*RST);
                float g2a[4] = {0,0,0,0}, g2b[4] = {0,0,0,0};
                uint32_t b4[4];
                #pragma unroll
                for (int kc2 = 0; kc2 < 2; kc2++){
                    ldsm4(b4, bahb + nofs + kc2*64);
                    mma16816(g2a, &fa1[0][(2*kc2)*4],   b4[0], b4[1]);
                    mma16816(g2b, &fa1[1][(2*kc2)*4],   b4[0], b4[1]);
                    mma16816(g2a, &fa1[0][(2*kc2+1)*4], b4[2], b4[3]);
                    mma16816(g2b, &fa1[1][(2*kc2+1)*4], b4[2], b4[3]);
                }
                #pragma unroll
                for (int kc2 = 0; kc2 < 2; kc2++){
                    ldsm4(b4, bbhb + nofs + kc2*64);
                    mma16816(g2a, &fa2[0][(2*kc2)*4],   b4[0], b4[1]);
                    mma16816(g2b, &fa2[1][(2*kc2)*4],   b4[0], b4[1]);
                    mma16816(g2a, &fa2[0][(2*kc2+1)*4], b4[2], b4[3]);
                    mma16816(g2b, &fa2[1][(2*kc2+1)*4], b4[2], b4[3]);
                }
                #pragma unroll
                for (int kc2 = 0; kc2 < 2; kc2++){
                    ldsm4(b4, balb + nofs + kc2*64);
                    mma16816(g2a, &fa1[0][(2*kc2)*4],   b4[0], b4[1]);
                    mma16816(g2b, &fa1[1][(2*kc2)*4],   b4[0], b4[1]);
                    mma16816(g2a, &fa1[0][(2*kc2+1)*4], b4[2], b4[3]);
                    mma16816(g2b, &fa1[1][(2*kc2+1)*4], b4[2], b4[3]);
                }
                #pragma unroll
                for (int kc2 = 0; kc2 < 2; kc2++){
                    ldsm4(b4, bblb + nofs + kc2*64);
                    mma16816(g2a, &fa2[0][(2*kc2)*4],   b4[0], b4[1]);
                    mma16816(g2b, &fa2[1][(2*kc2)*4],   b4[0], b4[1]);
                    mma16816(g2a, &fa2[0][(2*kc2+1)*4], b4[2], b4[3]);
                    mma16816(g2b, &fa2[1][(2*kc2+1)*4], b4[2], b4[3]);
                }
                // early slot release: all fa1 frags consumed by j==0's MMAs
                if (j == 0 && t < NT - 2) nbar_arrive(3 + s, 512);
                float h0 = epi_update(g2a, c2[0][j], p);
                float h1 = epi_update(g2b, c2[1][j], p);
                int u = 2*(ns + j) + (tig >> 1);
                if (u < 51){
                    a2w[er0*72 + u] = __float2half(h0);
                    a2w[er1*72 + u] = __float2half(h1);
                }
                pd0 = fmaf(h0, wlr[j], pd0);
                pd1 = fmaf(h1, wlr[j], pd1);
            }
            pd0 += __shfl_xor_sync(0xFFFFFFFFu, pd0, 2);
            pd1 += __shfl_xor_sync(0xFFFFFFFFu, pd1, 2);
            if (tig < 2){
                part[er0*8 + qy] = pd0;
                part[er1*8 + qy] = pd1;
            }
            nbar_sync(5, 320);                            // intra-Y: h2(t) + part done (drains STS)
            if (tid >= 256 && tid < 320){
                const int ot = tid - 256;
                const float* pr = part + ot*8;
                out[(size_t)(b0 + ot)*NT + t] =
                    (pr[0] + pr[1]) + (pr[2] + pr[3]) + pr[4] + blin0;
            }
            {
                const uint32_t a2r = ws ? a2base1 : a2base0;
                #pragma unroll
                for (int kc = 0; kc < 4; kc++){           // reload h2(t) from buffer ws
                    ldsm4(&fa2[0][kc*4], a2r + kc*32);
                    ldsm4(&fa2[1][kc*4], a2r + 16*RST + kc*32);
                }
            }
        }
    }
}

extern "C" void kernel_launch(void* const* d_in, const int* in_sizes, int n_in,
                              void* d_out, int out_size)
{
    (void)in_sizes; (void)n_in; (void)out_size;
    const float* input = (const float*)d_in[0];
    const float* Wih1  = (const float*)d_in[1];
    const float* Whh1  = (const float*)d_in[2];
    const float* bih1  = (const float*)d_in[3];
    const float* bhh1  = (const float*)d_in[4];
    const float* Wih2  = (const float*)d_in[5];
    const float* Whh2  = (const float*)d_in[6];
    const float* bih2  = (const float*)d_in[7];
    const float* bhh2  = (const float*)d_in[8];
    const float* Wlin  = (const float*)d_in[9];
    const float* blin  = (const float*)d_in[10];
    float* out = (float*)d_out;

    cudaFuncSetAttribute(lstm_ws_kernel, cudaFuncAttributeMaxDynamicSharedMemorySize, SMEM_TOTAL);
    lstm_ws_kernel<<<128, 512, SMEM_TOTAL>>>(input, Wih1, Whh1, bih1, bhh1,
                                             Wih2, Whh2, bih2, bhh2, Wlin, blin, out);
}

// round 12
// speedup vs baseline: 1.3701x; 1.3171x over previous
#include <cuda_runtime.h>
#include <cuda_fp16.h>
#include <cstdint>
#include <cstddef>

#define NT 2048
#define RST 144

// ---- smem layout (bytes) ----
#define BUF0   0          // h1 slot 0: [64][72] half
#define BUF1   9216       // h1 slot 1
#define A2H    18432      // h2 state
#define B1H    27648      // B tiles (fp16 hi only): 208*144 = 29952 each
#define B2AH   57600
#define B2BH   87552
#define O_WL   117504
#define O_PART 117760     // [64][8] float
#define SMEM_TOTAL 120832

__device__ __forceinline__ uint32_t s2u(const void* p){
    uint32_t a;
    asm("{ .reg .u64 t; cvta.to.shared.u64 t, %1; cvt.u32.u64 %0, t; }" : "=r"(a) : "l"(p));
    return a;
}
__device__ __forceinline__ void ldsm4(uint32_t* r, uint32_t a){
    asm volatile("ldmatrix.sync.aligned.m8n8.x4.shared.b16 {%0,%1,%2,%3}, [%4];"
        : "=r"(r[0]),"=r"(r[1]),"=r"(r[2]),"=r"(r[3]) : "r"(a));
}
__device__ __forceinline__ void mma16816(float* c, const uint32_t* a, uint32_t b0, uint32_t b1){
    asm volatile("mma.sync.aligned.m16n8k16.row.col.f32.f16.f16.f32 "
        "{%0,%1,%2,%3}, {%4,%5,%6,%7}, {%8,%9}, {%0,%1,%2,%3};"
        : "+f"(c[0]),"+f"(c[1]),"+f"(c[2]),"+f"(c[3])
        : "r"(a[0]),"r"(a[1]),"r"(a[2]),"r"(a[3]), "r"(b0),"r"(b1));
}
__device__ __forceinline__ void nbar_sync(int id, int cnt){
    asm volatile("bar.sync %0, %1;" :: "r"(id), "r"(cnt) : "memory");
}
__device__ __forceinline__ void nbar_arrive(int id, int cnt){
    asm volatile("bar.arrive %0, %1;" :: "r"(id), "r"(cnt) : "memory");
}
__device__ __forceinline__ float fast_sig(float x){
    float e = __expf(-x);
    float r;
    asm("rcp.approx.f32 %0, %1;" : "=f"(r) : "f"(1.0f + e));
    return r;
}
__device__ __forceinline__ float fast_tanh(float x){
    return fmaf(2.0f, fast_sig(x + x), -1.0f);
}
__device__ __forceinline__ float epi_update(const float* gc, float& c, int p){
    float r0 = __shfl_xor_sync(0xFFFFFFFFu, gc[0], 1);
    float r1 = __shfl_xor_sync(0xFFFFFFFFu, gc[1], 1);
    float r2 = __shfl_xor_sync(0xFFFFFFFFu, gc[2], 1);
    float r3 = __shfl_xor_sync(0xFFFFFFFFu, gc[3], 1);
    float gi = p ? r2 : gc[0];
    float gf = p ? r3 : gc[1];
    float gG = p ? gc[2] : r0;
    float gO = p ? gc[3] : r1;
    float cn = fast_sig(gf)*c + fast_sig(gi)*fast_tanh(gG);
    c = cn;
    return fast_sig(gO)*fast_tanh(cn);
}
// stage [204-row] weight block into [208][72] fp16 tile; cols [0,51)=W, 51=wx, 52=bias
__device__ void stageB(const float* W, const float* wx, const float* ba, const float* bb,
                       half* hi, int tid){
    for (int i = tid; i < 208*72; i += 512){
        int n = i / 72, k = i - n*72;
        float v = 0.0f;
        if (n < 204){
            int u = n >> 2, g = n & 3, row = g*51 + u;
            if (k < 51)                 v = W[row*51 + k];
            else if (k == 51 && wx)     v = wx[row];
            else if (k == 52 && ba)     v = ba[row] + bb[row];
        }
        hi[i] = __float2half(v);
    }
}

__global__ void __launch_bounds__(512, 1)
lstm_ws_kernel(const float* __restrict__ input,
               const float* __restrict__ Wih1, const float* __restrict__ Whh1,
               const float* __restrict__ bih1, const float* __restrict__ bhh1,
               const float* __restrict__ Wih2, const float* __restrict__ Whh2,
               const float* __restrict__ bih2, const float* __restrict__ bhh2,
               const float* __restrict__ Wlin, const float* __restrict__ blin,
               float* __restrict__ out)
{
    extern __shared__ char smem[];
    const int tid  = threadIdx.x;
    const int lane = tid & 31;
    const int wid  = tid >> 5;
    const int b0   = blockIdx.x * 64;
    const uint32_t sb = s2u(smem);

    half* buf[2] = { (half*)(smem + BUF0), (half*)(smem + BUF1) };
    half* a2h = (half*)(smem + A2H);

    // ---- init: stage weights, zero state ----
    stageB(Whh1, Wih1, bih1, bhh1, (half*)(smem + B1H),  tid);
    stageB(Wih2, 0,    bih2, bhh2, (half*)(smem + B2AH), tid);
    stageB(Whh2, 0,    0,    0,    (half*)(smem + B2BH), tid);
    for (int i = tid; i < 27648/4; i += 512) ((uint32_t*)(smem + BUF0))[i] = 0u;  // h1x2, h2
    for (int i = tid; i < 64*8; i += 512) ((float*)(smem + O_PART))[i] = 0.0f;
    if (tid < 52) ((float*)(smem + O_WL))[tid] = (tid < 51) ? Wlin[tid] : 0.0f;
    __syncthreads();
    if (tid < 64){
        buf[0][tid*72 + 51] = __float2half(input[(size_t)(b0 + tid)*NT]);  // x(0)
        buf[0][tid*72 + 52] = __float2half(1.0f);
        buf[1][tid*72 + 52] = __float2half(1.0f);
    }
    __syncthreads();

    const int g   = lane >> 2;
    const int tig = lane & 3;
    const int p   = tig & 1;
    const uint32_t aro  = (uint32_t)(((lane>>3)&1)*8*RST + (lane&7)*RST + ((lane>>4)&1)*16);
    const uint32_t bro4 = (uint32_t)((lane&7)*RST + ((lane>>3)&3)*16);
    const float* wlS = (const float*)(smem + O_WL);
    float* part = (float*)(smem + O_PART);

    if (wid < 6){
        // ================= X group: layer-1 recurrence (producer) =================
        const int mg = wid & 1, qx = wid >> 1;
        const int ns = qx * 9;
        const int nt = (qx == 2) ? 8 : 9;
        const int m0 = mg * 32;
        const int er0 = m0 + p*8 + g, er1 = er0 + 16;
        const uint32_t ab[2][2] = {
            { sb + BUF0 + m0*RST + aro, sb + BUF0 + m0*RST + aro + 16*RST },
            { sb + BUF1 + m0*RST + aro, sb + BUF1 + m0*RST + aro + 16*RST } };
        const uint32_t b1hb = sb + B1H + bro4;

        float c1[2][9];
        #pragma unroll
        for (int j = 0; j < 9; j++){ c1[0][j] = 0.0f; c1[1][j] = 0.0f; }

        uint32_t fa[2][16];
        #pragma unroll
        for (int kc = 0; kc < 4; kc++){
            ldsm4(&fa[0][kc*4], ab[0][0] + kc*32);
            ldsm4(&fa[1][kc*4], ab[0][1] + kc*32);
        }

        #pragma unroll 1
        for (int t = 0; t < NT; t++){
            const int s = t & 1;
            if (t >= 2) nbar_sync(3 + s, 512);            // wait slot s free
            float xv = 0.0f;
            if (tid < 64 && t + 1 < NT) xv = input[(size_t)(b0 + tid)*NT + t + 1];
            half* bh = buf[s];

            #pragma unroll
            for (int j = 0; j < 9; j++){
                if (j >= nt) break;
                const uint32_t nofs = (uint32_t)((ns + j)*8*RST);
                float g1a[4] = {0,0,0,0}, g1b[4] = {0,0,0,0};
                uint32_t b4[4];
                #pragma unroll
                for (int kc2 = 0; kc2 < 2; kc2++){
                    ldsm4(b4, b1hb + nofs + kc2*64);
                    mma16816(g1a, &fa[0][(2*kc2)*4],   b4[0], b4[1]);
                    mma16816(g1b, &fa[1][(2*kc2)*4],   b4[0], b4[1]);
                    mma16816(g1a, &fa[0][(2*kc2+1)*4], b4[2], b4[3]);
                    mma16816(g1b, &fa[1][(2*kc2+1)*4], b4[2], b4[3]);
                }
                float h0 = epi_update(g1a, c1[0][j], p);
                float h1 = epi_update(g1b, c1[1][j], p);
                int u = 2*(ns + j) + (tig >> 1);
                if (u < 51){
                    bh[er0*72 + u] = __float2half(h0);
                    bh[er1*72 + u] = __float2half(h1);
                }
            }
            if (tid < 64 && t + 1 < NT) bh[tid*72 + 51] = __float2half(xv);
            __threadfence_block();
            nbar_sync(6, 192);                            // intra-X: buf[s] complete
            nbar_arrive(1 + s, 512);                      // signal full[s] to Y
            #pragma unroll
            for (int kc = 0; kc < 4; kc++){               // reload h1(t) for t+1
                ldsm4(&fa[0][kc*4], ab[s][0] + kc*32);
                ldsm4(&fa[1][kc*4], ab[s][1] + kc*32);
            }
        }
    } else {
        // ================= Y group: layer-2 + output (consumer) =================
        const int yw = wid - 6;
        const int mg = yw & 1, qy = yw >> 1;
        const int nt = (qy == 0) ? 6 : 5;
        const int ns = (qy == 0) ? 0 : 6 + 5*(qy - 1);
        const int m0 = mg * 32;
        const int er0 = m0 + p*8 + g, er1 = er0 + 16;
        const uint32_t ab[2][2] = {
            { sb + BUF0 + m0*RST + aro, sb + BUF0 + m0*RST + aro + 16*RST },
            { sb + BUF1 + m0*RST + aro, sb + BUF1 + m0*RST + aro + 16*RST } };
        const uint32_t a2b0 = sb + A2H + m0*RST + aro, a2b1 = a2b0 + 16*RST;
        const uint32_t bahb = sb + B2AH + bro4;
        const uint32_t bbhb = sb + B2BH + bro4;
        const float blin0 = blin[0];

        float c2[2][6], wlr[6];
        #pragma unroll
        for (int j = 0; j < 6; j++){
            c2[0][j] = 0.0f; c2[1][j] = 0.0f;
            wlr[j] = wlS[2*(ns + j) + (tig >> 1)];
        }
        uint32_t fa1[2][16], fa2[2][16];
        #pragma unroll
        for (int kc = 0; kc < 4; kc++){                   // h2(-1) = 0
            ldsm4(&fa2[0][kc*4], a2b0 + kc*32);
            ldsm4(&fa2[1][kc*4], a2b1 + kc*32);
        }

        #pragma unroll 1
        for (int t = 0; t < NT; t++){
            const int s = t & 1;
            nbar_sync(1 + s, 512);                        // wait full[s]: h1(t) ready
            #pragma unroll
            for (int kc = 0; kc < 4; kc++){
                ldsm4(&fa1[0][kc*4], ab[s][0] + kc*32);
                ldsm4(&fa1[1][kc*4], ab[s][1] + kc*32);
            }
            float pd0 = 0.0f, pd1 = 0.0f;
            #pragma unroll
            for (int j = 0; j < 6; j++){
                if (j >= nt) break;
                const uint32_t nofs = (uint32_t)((ns + j)*8*RST);
                float g2a[4] = {0,0,0,0}, g2b[4] = {0,0,0,0};
                uint32_t b4[4];
                #pragma unroll
                for (int kc2 = 0; kc2 < 2; kc2++){
                    ldsm4(b4, bahb + nofs + kc2*64);
                    mma16816(g2a, &fa1[0][(2*kc2)*4],   b4[0], b4[1]);
                    mma16816(g2b, &fa1[1][(2*kc2)*4],   b4[0], b4[1]);
                    mma16816(g2a, &fa1[0][(2*kc2+1)*4], b4[2], b4[3]);
                    mma16816(g2b, &fa1[1][(2*kc2+1)*4], b4[2], b4[3]);
                }
                #pragma unroll
                for (int kc2 = 0; kc2 < 2; kc2++){
                    ldsm4(b4, bbhb + nofs + kc2*64);
                    mma16816(g2a, &fa2[0][(2*kc2)*4],   b4[0], b4[1]);
                    mma16816(g2b, &fa2[1][(2*kc2)*4],   b4[0], b4[1]);
                    mma16816(g2a, &fa2[0][(2*kc2+1)*4], b4[2], b4[3]);
                    mma16816(g2b, &fa2[1][(2*kc2+1)*4], b4[2], b4[3]);
                }
                float h0 = epi_update(g2a, c2[0][j], p);
                float h1 = epi_update(g2b, c2[1][j], p);
                int u = 2*(ns + j) + (tig >> 1);
                if (u < 51){
                    a2h[er0*72 + u] = __float2half(h0);
                    a2h[er1*72 + u] = __float2half(h1);
                }
                pd0 = fmaf(h0, wlr[j], pd0);
                pd1 = fmaf(h1, wlr[j], pd1);
            }
            pd0 += __shfl_xor_sync(0xFFFFFFFFu, pd0, 2);
            pd1 += __shfl_xor_sync(0xFFFFFFFFu, pd1, 2);
            if (tig < 2){
                part[er0*8 + qy] = pd0;
                part[er1*8 + qy] = pd1;
            }
            __threadfence_block();
            nbar_sync(5, 320);                            // intra-Y: a2h + part done
            if (tid >= 256 && tid < 320){
                const int ot = tid - 256;
                const float* pr = part + ot*8;
                out[(size_t)(b0 + ot)*NT + t] =
                    (pr[0] + pr[1]) + (pr[2] + pr[3]) + pr[4] + blin0;
            }
            #pragma unroll
            for (int kc = 0; kc < 4; kc++){               // reload h2(t) for t+1
                ldsm4(&fa2[0][kc*4], a2b0 + kc*32);
                ldsm4(&fa2[1][kc*4], a2b1 + kc*32);
            }
            nbar_sync(5, 320);                            // guard fa2 loads vs next writes
            if (t < NT - 2) nbar_arrive(3 + s, 512);      // release slot s to X
        }
    }
}

extern "C" void kernel_launch(void* const* d_in, const int* in_sizes, int n_in,
                              void* d_out, int out_size)
{
    (void)in_sizes; (void)n_in; (void)out_size;
    const float* input = (const float*)d_in[0];
    const float* Wih1  = (const float*)d_in[1];
    const float* Whh1  = (const float*)d_in[2];
    const float* bih1  = (const float*)d_in[3];
    const float* bhh1  = (const float*)d_in[4];
    const float* Wih2  = (const float*)d_in[5];
    const float* Whh2  = (const float*)d_in[6];
    const float* bih2  = (const float*)d_in[7];
    const float* bhh2  = (const float*)d_in[8];
    const float* Wlin  = (const float*)d_in[9];
    const float* blin  = (const float*)d_in[10];
    float* out = (float*)d_out;

    cudaFuncSetAttribute(lstm_ws_kernel, cudaFuncAttributeMaxDynamicSharedMemorySize, SMEM_TOTAL);
    lstm_ws_kernel<<<128, 512, SMEM_TOTAL>>>(input, Wih1, Whh1, bih1, bhh1,
                                             Wih2, Whh2, bih2, bhh2, Wlin, blin, out);
}

// round 13
// speedup vs baseline: 2.0012x; 1.4606x over previous
#include <cuda_runtime.h>
#include <cuda_fp16.h>
#include <cstdint>
#include <cstddef>

#define NT 2048
#define RST 144

// ---- smem layout (bytes) ----
#define BUF0   0          // h1 slot 0: [64][72] half
#define BUF1   9216       // h1 slot 1
#define A2H    18432      // h2 state
#define B1H    27648      // B tiles (fp16): 208*144 = 29952 each
#define B2AH   57600
#define B2BH   87552
#define O_WL   117504
#define O_PART 117760     // [64][8] float
#define SMEM_TOTAL 120832

__device__ __forceinline__ uint32_t s2u(const void* p){
    uint32_t a;
    asm("{ .reg .u64 t; cvta.to.shared.u64 t, %1; cvt.u32.u64 %0, t; }" : "=r"(a) : "l"(p));
    return a;
}
__device__ __forceinline__ void ldsm4(uint32_t* r, uint32_t a){
    asm volatile("ldmatrix.sync.aligned.m8n8.x4.shared.b16 {%0,%1,%2,%3}, [%4];"
        : "=r"(r[0]),"=r"(r[1]),"=r"(r[2]),"=r"(r[3]) : "r"(a));
}
__device__ __forceinline__ void mma16816(float* c, const uint32_t* a, uint32_t b0, uint32_t b1){
    asm volatile("mma.sync.aligned.m16n8k16.row.col.f32.f16.f16.f32 "
        "{%0,%1,%2,%3}, {%4,%5,%6,%7}, {%8,%9}, {%0,%1,%2,%3};"
        : "+f"(c[0]),"+f"(c[1]),"+f"(c[2]),"+f"(c[3])
        : "r"(a[0]),"r"(a[1]),"r"(a[2]),"r"(a[3]), "r"(b0),"r"(b1));
}
__device__ __forceinline__ void nbar_sync(int id, int cnt){
    asm volatile("bar.sync %0, %1;" :: "r"(id), "r"(cnt) : "memory");
}
__device__ __forceinline__ void nbar_arrive(int id, int cnt){
    asm volatile("bar.arrive %0, %1;" :: "r"(id), "r"(cnt) : "memory");
}
// HW tanh unit: 1 MUFU op (plain PTX, sm_75+)
__device__ __forceinline__ float tanh_ap(float x){
    float r;
    asm("tanh.approx.f32 %0, %1;" : "=f"(r) : "f"(x));
    return r;
}
__device__ __forceinline__ float fast_sig(float x){
    return fmaf(0.5f, tanh_ap(0.5f * x), 0.5f);   // exact identity
}
__device__ __forceinline__ float fast_tanh(float x){
    return tanh_ap(x);
}
__device__ __forceinline__ float epi_update(const float* gc, float& c, int p){
    float r0 = __shfl_xor_sync(0xFFFFFFFFu, gc[0], 1);
    float r1 = __shfl_xor_sync(0xFFFFFFFFu, gc[1], 1);
    float r2 = __shfl_xor_sync(0xFFFFFFFFu, gc[2], 1);
    float r3 = __shfl_xor_sync(0xFFFFFFFFu, gc[3], 1);
    float gi = p ? r2 : gc[0];
    float gf = p ? r3 : gc[1];
    float gG = p ? gc[2] : r0;
    float gO = p ? gc[3] : r1;
    float cn = fast_sig(gf)*c + fast_sig(gi)*fast_tanh(gG);
    c = cn;
    return fast_sig(gO)*fast_tanh(cn);
}
// stage [204-row] weight block into [208][72] fp16 tile; cols [0,51)=W, 51=wx, 52=bias
__device__ void stageB(const float* W, const float* wx, const float* ba, const float* bb,
                       half* hi, int tid){
    for (int i = tid; i < 208*72; i += 512){
        int n = i / 72, k = i - n*72;
        float v = 0.0f;
        if (n < 204){
            int u = n >> 2, g = n & 3, row = g*51 + u;
            if (k < 51)                 v = W[row*51 + k];
            else if (k == 51 && wx)     v = wx[row];
            else if (k == 52 && ba)     v = ba[row] + bb[row];
        }
        hi[i] = __float2half(v);
    }
}

__global__ void __launch_bounds__(512, 1)
lstm_ws_kernel(const float* __restrict__ input,
               const float* __restrict__ Wih1, const float* __restrict__ Whh1,
               const float* __restrict__ bih1, const float* __restrict__ bhh1,
               const float* __restrict__ Wih2, const float* __restrict__ Whh2,
               const float* __restrict__ bih2, const float* __restrict__ bhh2,
               const float* __restrict__ Wlin, const float* __restrict__ blin,
               float* __restrict__ out)
{
    extern __shared__ char smem[];
    const int tid  = threadIdx.x;
    const int lane = tid & 31;
    const int wid  = tid >> 5;
    const int b0   = blockIdx.x * 64;
    const uint32_t sb = s2u(smem);

    half* buf[2] = { (half*)(smem + BUF0), (half*)(smem + BUF1) };
    half* a2h = (half*)(smem + A2H);

    // ---- init: stage weights, zero state ----
    stageB(Whh1, Wih1, bih1, bhh1, (half*)(smem + B1H),  tid);
    stageB(Wih2, 0,    bih2, bhh2, (half*)(smem + B2AH), tid);
    stageB(Whh2, 0,    0,    0,    (half*)(smem + B2BH), tid);
    for (int i = tid; i < 27648/4; i += 512) ((uint32_t*)(smem + BUF0))[i] = 0u;  // h1x2, h2
    for (int i = tid; i < 64*8; i += 512) ((float*)(smem + O_PART))[i] = 0.0f;
    if (tid < 52) ((float*)(smem + O_WL))[tid] = (tid < 51) ? Wlin[tid] : 0.0f;
    __syncthreads();
    if (tid < 64){
        buf[0][tid*72 + 51] = __float2half(input[(size_t)(b0 + tid)*NT]);  // x(0)
        buf[0][tid*72 + 52] = __float2half(1.0f);
        buf[1][tid*72 + 52] = __float2half(1.0f);
    }
    __syncthreads();

    const int g   = lane >> 2;
    const int tig = lane & 3;
    const int p   = tig & 1;
    const uint32_t aro  = (uint32_t)(((lane>>3)&1)*8*RST + (lane&7)*RST + ((lane>>4)&1)*16);
    const uint32_t bro4 = (uint32_t)((lane&7)*RST + ((lane>>3)&3)*16);
    const float* wlS = (const float*)(smem + O_WL);
    float* part = (float*)(smem + O_PART);

    if (wid < 6){
        // ================= X group: layer-1 recurrence (producer) =================
        const int mg = wid & 1, qx = wid >> 1;
        const int ns = qx * 9;
        const int nt = (qx == 2) ? 8 : 9;
        const int m0 = mg * 32;
        const int er0 = m0 + p*8 + g, er1 = er0 + 16;
        const uint32_t ab[2][2] = {
            { sb + BUF0 + m0*RST + aro, sb + BUF0 + m0*RST + aro + 16*RST },
            { sb + BUF1 + m0*RST + aro, sb + BUF1 + m0*RST + aro + 16*RST } };
        const uint32_t b1hb = sb + B1H + bro4;

        float c1[2][9];
        #pragma unroll
        for (int j = 0; j < 9; j++){ c1[0][j] = 0.0f; c1[1][j] = 0.0f; }

        uint32_t fa[2][16];
        #pragma unroll
        for (int kc = 0; kc < 4; kc++){
            ldsm4(&fa[0][kc*4], ab[0][0] + kc*32);
            ldsm4(&fa[1][kc*4], ab[0][1] + kc*32);
        }

        #pragma unroll 1
        for (int t = 0; t < NT; t++){
            const int s = t & 1;
            if (t >= 2) nbar_sync(3 + s, 512);            // wait slot s free
            float xv = 0.0f;
            if (tid < 64 && t + 1 < NT) xv = input[(size_t)(b0 + tid)*NT + t + 1];
            half* bh = buf[s];

            #pragma unroll
            for (int j = 0; j < 9; j++){
                if (j >= nt) break;
                const uint32_t nofs = (uint32_t)((ns + j)*8*RST);
                float g1a[4] = {0,0,0,0}, g1b[4] = {0,0,0,0};
                uint32_t b4[4];
                #pragma unroll
                for (int kc2 = 0; kc2 < 2; kc2++){
                    ldsm4(b4, b1hb + nofs + kc2*64);
                    mma16816(g1a, &fa[0][(2*kc2)*4],   b4[0], b4[1]);
                    mma16816(g1b, &fa[1][(2*kc2)*4],   b4[0], b4[1]);
                    mma16816(g1a, &fa[0][(2*kc2+1)*4], b4[2], b4[3]);
                    mma16816(g1b, &fa[1][(2*kc2+1)*4], b4[2], b4[3]);
                }
                float h0 = epi_update(g1a, c1[0][j], p);
                float h1 = epi_update(g1b, c1[1][j], p);
                int u = 2*(ns + j) + (tig >> 1);
                if (u < 51){
                    bh[er0*72 + u] = __float2half(h0);
                    bh[er1*72 + u] = __float2half(h1);
                }
            }
            if (tid < 64 && t + 1 < NT) bh[tid*72 + 51] = __float2half(xv);
            __threadfence_block();
            nbar_sync(6, 192);                            // intra-X: buf[s] complete
            nbar_arrive(1 + s, 512);                      // signal full[s] to Y
            #pragma unroll
            for (int kc = 0; kc < 4; kc++){               // reload h1(t) for t+1
                ldsm4(&fa[0][kc*4], ab[s][0] + kc*32);
                ldsm4(&fa[1][kc*4], ab[s][1] + kc*32);
            }
        }
    } else {
        // ================= Y group: layer-2 + output (consumer) =================
        const int yw = wid - 6;
        const int mg = yw & 1, qy = yw >> 1;
        const int nt = (qy == 0) ? 6 : 5;
        const int ns = (qy == 0) ? 0 : 6 + 5*(qy - 1);
        const int m0 = mg * 32;
        const int er0 = m0 + p*8 + g, er1 = er0 + 16;
        const uint32_t ab[2][2] = {
            { sb + BUF0 + m0*RST + aro, sb + BUF0 + m0*RST + aro + 16*RST },
            { sb + BUF1 + m0*RST + aro, sb + BUF1 + m0*RST + aro + 16*RST } };
        const uint32_t a2b0 = sb + A2H + m0*RST + aro, a2b1 = a2b0 + 16*RST;
        const uint32_t bahb = sb + B2AH + bro4;
        const uint32_t bbhb = sb + B2BH + bro4;
        const float blin0 = blin[0];

        float c2[2][6], wlr[6];
        #pragma unroll
        for (int j = 0; j < 6; j++){
            c2[0][j] = 0.0f; c2[1][j] = 0.0f;
            wlr[j] = wlS[2*(ns + j) + (tig >> 1)];
        }
        uint32_t fa1[2][16], fa2[2][16];
        #pragma unroll
        for (int kc = 0; kc < 4; kc++){                   // h2(-1) = 0
            ldsm4(&fa2[0][kc*4], a2b0 + kc*32);
            ldsm4(&fa2[1][kc*4], a2b1 + kc*32);
        }

        #pragma unroll 1
        for (int t = 0; t < NT; t++){
            const int s = t & 1;
            nbar_sync(1 + s, 512);                        // wait full[s]: h1(t) ready
            #pragma unroll
            for (int kc = 0; kc < 4; kc++){
                ldsm4(&fa1[0][kc*4], ab[s][0] + kc*32);
                ldsm4(&fa1[1][kc*4], ab[s][1] + kc*32);
            }
            float pd0 = 0.0f, pd1 = 0.0f;
            #pragma unroll
            for (int j = 0; j < 6; j++){
                if (j >= nt) break;
                const uint32_t nofs = (uint32_t)((ns + j)*8*RST);
                float g2a[4] = {0,0,0,0}, g2b[4] = {0,0,0,0};
                uint32_t b4[4];
                #pragma unroll
                for (int kc2 = 0; kc2 < 2; kc2++){
                    ldsm4(b4, bahb + nofs + kc2*64);
                    mma16816(g2a, &fa1[0][(2*kc2)*4],   b4[0], b4[1]);
                    mma16816(g2b, &fa1[1][(2*kc2)*4],   b4[0], b4[1]);
                    mma16816(g2a, &fa1[0][(2*kc2+1)*4], b4[2], b4[3]);
                    mma16816(g2b, &fa1[1][(2*kc2+1)*4], b4[2], b4[3]);
                }
                #pragma unroll
                for (int kc2 = 0; kc2 < 2; kc2++){
                    ldsm4(b4, bbhb + nofs + kc2*64);
                    mma16816(g2a, &fa2[0][(2*kc2)*4],   b4[0], b4[1]);
                    mma16816(g2b, &fa2[1][(2*kc2)*4],   b4[0], b4[1]);
                    mma16816(g2a, &fa2[0][(2*kc2+1)*4], b4[2], b4[3]);
                    mma16816(g2b, &fa2[1][(2*kc2+1)*4], b4[2], b4[3]);
                }
                float h0 = epi_update(g2a, c2[0][j], p);
                float h1 = epi_update(g2b, c2[1][j], p);
                int u = 2*(ns + j) + (tig >> 1);
                if (u < 51){
                    a2h[er0*72 + u] = __float2half(h0);
                    a2h[er1*72 + u] = __float2half(h1);
                }
                pd0 = fmaf(h0, wlr[j], pd0);
                pd1 = fmaf(h1, wlr[j], pd1);
            }
            pd0 += __shfl_xor_sync(0xFFFFFFFFu, pd0, 2);
            pd1 += __shfl_xor_sync(0xFFFFFFFFu, pd1, 2);
            if (tig < 2){
                part[er0*8 + qy] = pd0;
                part[er1*8 + qy] = pd1;
            }
            __threadfence_block();
            nbar_sync(5, 320);                            // intra-Y: a2h + part done
            if (tid >= 256 && tid < 320){
                const int ot = tid - 256;
                const float* pr = part + ot*8;
                out[(size_t)(b0 + ot)*NT + t] =
                    (pr[0] + pr[1]) + (pr[2] + pr[3]) + pr[4] + blin0;
            }
            #pragma unroll
            for (int kc = 0; kc < 4; kc++){               // reload h2(t) for t+1
                ldsm4(&fa2[0][kc*4], a2b0 + kc*32);
                ldsm4(&fa2[1][kc*4], a2b1 + kc*32);
            }
            nbar_sync(5, 320);                            // guard fa2 loads vs next writes
            if (t < NT - 2) nbar_arrive(3 + s, 512);      // release slot s to X
        }
    }
}

extern "C" void kernel_launch(void* const* d_in, const int* in_sizes, int n_in,
                              void* d_out, int out_size)
{
    (void)in_sizes; (void)n_in; (void)out_size;
    const float* input = (const float*)d_in[0];
    const float* Wih1  = (const float*)d_in[1];
    const float* Whh1  = (const float*)d_in[2];
    const float* bih1  = (const float*)d_in[3];
    const float* bhh1  = (const float*)d_in[4];
    const float* Wih2  = (const float*)d_in[5];
    const float* Whh2  = (const float*)d_in[6];
    const float* bih2  = (const float*)d_in[7];
    const float* bhh2  = (const float*)d_in[8];
    const float* Wlin  = (const float*)d_in[9];
    const float* blin  = (const float*)d_in[10];
    float* out = (float*)d_out;

    cudaFuncSetAttribute(lstm_ws_kernel, cudaFuncAttributeMaxDynamicSharedMemorySize, SMEM_TOTAL);
    lstm_ws_kernel<<<128, 512, SMEM_TOTAL>>>(input, Wih1, Whh1, bih1, bhh1,
                                             Wih2, Whh2, bih2, bhh2, Wlin, blin, out);
}